// round 16
// baseline (speedup 1.0000x reference)
#include <cuda_runtime.h>
#include <cuda_bf16.h>
#include <math.h>
#include <stdint.h>

// Problem constants
#define BB 4
#define CC 256
#define NN_ 1024
#define HH 8
#define DD 256
#define HD 2048
#define ZZ 32   // B*H

// GEMM tiling: CTA 128x128, 8 warps of 32x64 (proven config)
#define BM 128
#define BN 128
#define BK 32
#define LDA 40                 // padded row length (bf16 elems) = 80 B
#define TILE_E (128 * LDA)
#define STAGE_E (4 * TILE_E)
#define SMEM_BYTES (2 * STAGE_E * 2)

// attn_o tiling: CTA 64x128, 8 warps of 32x32, 3-stage pipeline
#define OM 64
#define TILE_O ((OM + BN) * LDA)
#define STAGE_O (2 * TILE_O)
#define SMEM_O_BYTES (3 * STAGE_O * 2)

// k-major tiling (attn_s), 3-stage pipeline
#define LDB_KT 136
#define TILE_KT (32 * LDB_KT)
#define STAGE_KT (4 * TILE_KT)
#define SMEM_S_BYTES (3 * STAGE_KT * 2)

// ---------------- scratch ----------------------------------------------------
__device__ __align__(256) float g_YP[(size_t)BB * CC * NN_];
__device__ __align__(256) float g_S[(size_t)ZZ * NN_ * NN_];

__device__ __align__(256) __nv_bfloat16 g_Wqh[(size_t)HD * CC];
__device__ __align__(256) __nv_bfloat16 g_Wql[(size_t)HD * CC];
__device__ __align__(256) __nv_bfloat16 g_Wkh[(size_t)HD * CC];
__device__ __align__(256) __nv_bfloat16 g_Wkl[(size_t)HD * CC];
__device__ __align__(256) __nv_bfloat16 g_Wvh[(size_t)HD * CC];
__device__ __align__(256) __nv_bfloat16 g_Wvl[(size_t)HD * CC];
__device__ __align__(256) __nv_bfloat16 g_Wph[(size_t)CC * CC];
__device__ __align__(256) __nv_bfloat16 g_Wpl[(size_t)CC * CC];

__device__ __align__(256) __nv_bfloat16 g_Xth[(size_t)BB * NN_ * CC];
__device__ __align__(256) __nv_bfloat16 g_Xtl[(size_t)BB * NN_ * CC];
__device__ __align__(256) __nv_bfloat16 g_Yth[(size_t)BB * NN_ * CC];
__device__ __align__(256) __nv_bfloat16 g_Ytl[(size_t)BB * NN_ * CC];

__device__ __align__(256) __nv_bfloat16 g_Qh[(size_t)BB * HD * NN_];
__device__ __align__(256) __nv_bfloat16 g_Ql[(size_t)BB * HD * NN_];
__device__ __align__(256) __nv_bfloat16 g_Kh[(size_t)BB * HD * NN_];
__device__ __align__(256) __nv_bfloat16 g_Kl[(size_t)BB * HD * NN_];
__device__ __align__(256) __nv_bfloat16 g_Vh[(size_t)BB * HD * NN_];
__device__ __align__(256) __nv_bfloat16 g_Vl[(size_t)BB * HD * NN_];

__device__ __align__(256) __nv_bfloat16 g_Ph[(size_t)ZZ * NN_ * NN_];
__device__ __align__(256) __nv_bfloat16 g_Pl[(size_t)ZZ * NN_ * NN_];

// ---------------- helpers ----------------------------------------------------
__device__ __forceinline__ uint32_t smem_u32(const void* p) {
    uint32_t a;
    asm("{ .reg .u64 t; cvta.to.shared.u64 t, %1; cvt.u32.u64 %0, t; }"
        : "=r"(a) : "l"(p));
    return a;
}
__device__ __forceinline__ void ldsm_x4(uint32_t* r, uint32_t addr) {
    asm volatile("ldmatrix.sync.aligned.m8n8.x4.shared.b16 {%0,%1,%2,%3}, [%4];"
                 : "=r"(r[0]), "=r"(r[1]), "=r"(r[2]), "=r"(r[3]) : "r"(addr));
}
__device__ __forceinline__ void ldsm_x4_t(uint32_t* r, uint32_t addr) {
    asm volatile("ldmatrix.sync.aligned.m8n8.x4.trans.shared.b16 {%0,%1,%2,%3}, [%4];"
                 : "=r"(r[0]), "=r"(r[1]), "=r"(r[2]), "=r"(r[3]) : "r"(addr));
}
__device__ __forceinline__ void mma_bf16(float* c, const uint32_t* a, const uint32_t* b) {
    asm volatile(
        "mma.sync.aligned.m16n8k16.row.col.f32.bf16.bf16.f32 "
        "{%0,%1,%2,%3}, {%4,%5,%6,%7}, {%8,%9}, {%0,%1,%2,%3};"
        : "+f"(c[0]), "+f"(c[1]), "+f"(c[2]), "+f"(c[3])
        : "r"(a[0]), "r"(a[1]), "r"(a[2]), "r"(a[3]), "r"(b[0]), "r"(b[1]));
}
__device__ __forceinline__ void cp_async16(uint32_t sm, const void* g) {
    asm volatile("cp.async.cg.shared.global [%0], [%1], 16;" :: "r"(sm), "l"(g));
}
__device__ __forceinline__ void cp_commit() {
    asm volatile("cp.async.commit_group;" ::: "memory");
}
__device__ __forceinline__ void cp_wait1() {
    asm volatile("cp.async.wait_group 1;" ::: "memory");
}
__device__ __forceinline__ void cp_wait0() {
    asm volatile("cp.async.wait_group 0;" ::: "memory");
}

// ===========================================================================
// j-major mainloop (proj): 256 threads, 8 warps of 32x64, 2-stage (proven)
// ===========================================================================
__device__ __forceinline__ void issue_stage(
    uint32_t sbase,
    const __nv_bfloat16* gAh, const __nv_bfloat16* gAl, size_t strideA,
    const __nv_bfloat16* gBh, const __nv_bfloat16* gBl, size_t strideB,
    int k0, int tid)
{
    const int r = tid >> 2;
    const int q = tid & 3;
    const uint32_t so = (uint32_t)((r * LDA + q * 8) * 2);
    const uint32_t so2 = (uint32_t)(((r + 64) * LDA + q * 8) * 2);
    const size_t go = (size_t)r * strideA + k0 + q * 8;
    const size_t go2 = (size_t)(r + 64) * strideA + k0 + q * 8;
    const size_t gb = (size_t)r * strideB + k0 + q * 8;
    const size_t gb2 = (size_t)(r + 64) * strideB + k0 + q * 8;

    cp_async16(sbase + so, gAh + go);
    cp_async16(sbase + so2, gAh + go2);
    cp_async16(sbase + TILE_E * 2 + so, gAl + go);
    cp_async16(sbase + TILE_E * 2 + so2, gAl + go2);
    cp_async16(sbase + 2 * TILE_E * 2 + so, gBh + gb);
    cp_async16(sbase + 2 * TILE_E * 2 + so2, gBh + gb2);
    cp_async16(sbase + 3 * TILE_E * 2 + so, gBl + gb);
    cp_async16(sbase + 3 * TILE_E * 2 + so2, gBl + gb2);
}

__device__ __forceinline__ void mma_mainloop(
    const __nv_bfloat16* __restrict__ gAh, const __nv_bfloat16* __restrict__ gAl,
    size_t strideA,
    const __nv_bfloat16* __restrict__ gBh, const __nv_bfloat16* __restrict__ gBl,
    size_t strideB,
    int KTOT, char* smem, float acc[2][8][4])
{
    const int tid = threadIdx.x;
    const int lane = tid & 31, wid = tid >> 5;
    const int wm = (wid & 3) * 32;
    const int wn = (wid >> 2) * 64;

    const uint32_t sb = smem_u32(smem);

    const int a_row = lane & 15;
    const int a_col = (lane >> 4) * 8;
    const int b_row = (lane & 7) + (lane >> 4) * 8;
    const int b_col = ((lane >> 3) & 1) * 8;

    const int iters = KTOT / BK;

    issue_stage(sb, gAh, gAl, strideA, gBh, gBl, strideB, 0, tid);
    cp_commit();

    for (int it = 0; it < iters; it++) {
        if (it + 1 < iters) {
            issue_stage(sb + ((it + 1) & 1) * STAGE_E * 2,
                        gAh, gAl, strideA, gBh, gBl, strideB, (it + 1) * BK, tid);
            cp_commit();
            cp_wait1();
        } else {
            cp_wait0();
        }
        __syncthreads();

        const uint32_t st = sb + (it & 1) * STAGE_E * 2;
#pragma unroll
        for (int kk = 0; kk < BK; kk += 16) {
            uint32_t ah[2][4], al[2][4];
#pragma unroll
            for (int mt = 0; mt < 2; mt++) {
                uint32_t ra = st + (uint32_t)(((wm + mt * 16 + a_row) * LDA + kk + a_col) * 2);
                ldsm_x4(ah[mt], ra);
                ldsm_x4(al[mt], ra + TILE_E * 2);
            }
#pragma unroll
            for (int g = 0; g < 4; g++) {
                uint32_t bh[4], bl[4];
                uint32_t rb = st + 2 * TILE_E * 2 +
                              (uint32_t)(((wn + g * 16 + b_row) * LDA + kk + b_col) * 2);
                ldsm_x4(bh, rb);
                ldsm_x4(bl, rb + TILE_E * 2);
#pragma unroll
                for (int half = 0; half < 2; half++) {
                    const int u = half * 2;
                    const int nt = g * 2 + half;
#pragma unroll
                    for (int mt = 0; mt < 2; mt++) {
                        mma_bf16(acc[mt][nt], ah[mt], &bh[u]);
                        mma_bf16(acc[mt][nt], ah[mt], &bl[u]);
                        mma_bf16(acc[mt][nt], al[mt], &bh[u]);
                    }
                }
            }
        }
        __syncthreads();
    }
}

// ===========================================================================
// Merged projection: grid (8, 50, B). y>>4: 0->Q, 1->K, 2->V, y>=48 -> Wp(YP)
// ===========================================================================
__global__ void __launch_bounds__(256) proj_all_kernel(
    const __nv_bfloat16* __restrict__ Wqh, const __nv_bfloat16* __restrict__ Wql,
    const __nv_bfloat16* __restrict__ Wkh, const __nv_bfloat16* __restrict__ Wkl,
    const __nv_bfloat16* __restrict__ Wvh, const __nv_bfloat16* __restrict__ Wvl,
    const __nv_bfloat16* __restrict__ Wph, const __nv_bfloat16* __restrict__ Wpl,
    const __nv_bfloat16* __restrict__ Xh, const __nv_bfloat16* __restrict__ Xl,
    const __nv_bfloat16* __restrict__ Yh, const __nv_bfloat16* __restrict__ Yl,
    const float* __restrict__ bq, const float* __restrict__ bk,
    const float* __restrict__ bv,
    __nv_bfloat16* __restrict__ Qh, __nv_bfloat16* __restrict__ Ql,
    __nv_bfloat16* __restrict__ Kh, __nv_bfloat16* __restrict__ Kl,
    __nv_bfloat16* __restrict__ Vh, __nv_bfloat16* __restrict__ Vl,
    float* __restrict__ YP)
{
    extern __shared__ char smem[];
    const int z = blockIdx.z;
    const int yb = blockIdx.y;
    const int n0 = blockIdx.x * BN;

    const __nv_bfloat16 *Wh, *Wl, *Ih, *Il;
    const float* bias = nullptr;
    __nv_bfloat16 *outH = nullptr, *outL = nullptr;
    float* outF = nullptr;
    int m0;
    if (yb < 16)      { Wh = Wqh; Wl = Wql; Ih = Xh; Il = Xl; bias = bq; outH = Qh; outL = Ql; m0 = yb * BM; }
    else if (yb < 32) { Wh = Wkh; Wl = Wkl; Ih = Xh; Il = Xl; bias = bk; outH = Kh; outL = Kl; m0 = (yb - 16) * BM; }
    else if (yb < 48) { Wh = Wvh; Wl = Wvl; Ih = Yh; Il = Yl; bias = bv; outH = Vh; outL = Vl; m0 = (yb - 32) * BM; }
    else              { Wh = Wph; Wl = Wpl; Ih = Yh; Il = Yl; outF = YP; m0 = (yb - 48) * BM; }

    float acc[2][8][4] = {};
    mma_mainloop(Wh + (size_t)m0 * CC, Wl + (size_t)m0 * CC, CC,
                 Ih + ((size_t)z * NN_ + n0) * CC, Il + ((size_t)z * NN_ + n0) * CC, CC,
                 CC, smem, acc);

    const int lane = threadIdx.x & 31, wid = threadIdx.x >> 5;
    const int wm = (wid & 3) * 32, wn = (wid >> 2) * 64;
#pragma unroll
    for (int mt = 0; mt < 2; mt++)
#pragma unroll
        for (int nt = 0; nt < 8; nt++) {
            int m = m0 + wm + mt * 16 + (lane >> 2);
            int n = n0 + wn + nt * 8 + 2 * (lane & 3);
            if (outF) {
                *reinterpret_cast<float2*>(&outF[((size_t)z * CC + m) * NN_ + n]) =
                    make_float2(acc[mt][nt][0], acc[mt][nt][1]);
                *reinterpret_cast<float2*>(&outF[((size_t)z * CC + m + 8) * NN_ + n]) =
                    make_float2(acc[mt][nt][2], acc[mt][nt][3]);
            } else {
                float b0 = bias[m], b1 = bias[m + 8];
                float v00 = acc[mt][nt][0] + b0, v01 = acc[mt][nt][1] + b0;
                float v10 = acc[mt][nt][2] + b1, v11 = acc[mt][nt][3] + b1;
                __nv_bfloat16 h00 = __float2bfloat16(v00), h01 = __float2bfloat16(v01);
                __nv_bfloat16 h10 = __float2bfloat16(v10), h11 = __float2bfloat16(v11);
                __nv_bfloat162 hp0; hp0.x = h00; hp0.y = h01;
                __nv_bfloat162 hp1; hp1.x = h10; hp1.y = h11;
                __nv_bfloat162 lp0;
                lp0.x = __float2bfloat16(v00 - __bfloat162float(h00));
                lp0.y = __float2bfloat16(v01 - __bfloat162float(h01));
                __nv_bfloat162 lp1;
                lp1.x = __float2bfloat16(v10 - __bfloat162float(h10));
                lp1.y = __float2bfloat16(v11 - __bfloat162float(h11));
                *reinterpret_cast<__nv_bfloat162*>(&outH[((size_t)z * HD + m) * NN_ + n]) = hp0;
                *reinterpret_cast<__nv_bfloat162*>(&outH[((size_t)z * HD + m + 8) * NN_ + n]) = hp1;
                *reinterpret_cast<__nv_bfloat162*>(&outL[((size_t)z * HD + m) * NN_ + n]) = lp0;
                *reinterpret_cast<__nv_bfloat162*>(&outL[((size_t)z * HD + m + 8) * NN_ + n]) = lp1;
            }
        }
}

// ===========================================================================
// attn_s: S = Q^T K, k-major operands, trans ldsm, 3-stage pipeline,
// register-capped for 2 CTAs/SM. grid (8, 8, 32)
// ===========================================================================
__device__ __forceinline__ void issue_stage_kt(
    uint32_t sbase,
    const __nv_bfloat16* gAh, const __nv_bfloat16* gAl,
    const __nv_bfloat16* gBh, const __nv_bfloat16* gBl,
    int k0, int tid)
{
    const int r = tid >> 4;
    const int c = tid & 15;
#pragma unroll
    for (int p = 0; p < 2; p++) {
        const int row = r + p * 16;
        const uint32_t so = (uint32_t)((row * LDB_KT + c * 8) * 2);
        const size_t go = (size_t)(k0 + row) * NN_ + c * 8;
        cp_async16(sbase + so, gAh + go);
        cp_async16(sbase + TILE_KT * 2 + so, gAl + go);
        cp_async16(sbase + 2 * TILE_KT * 2 + so, gBh + go);
        cp_async16(sbase + 3 * TILE_KT * 2 + so, gBl + go);
    }
}

__global__ void __launch_bounds__(256, 2) attn_s_kernel(
    const __nv_bfloat16* __restrict__ Qh, const __nv_bfloat16* __restrict__ Ql,
    const __nv_bfloat16* __restrict__ Kh, const __nv_bfloat16* __restrict__ Kl,
    float* __restrict__ S)
{
    extern __shared__ char smem[];
    const int tid = threadIdx.x;
    const int lane = tid & 31, wid = tid >> 5;
    const int z = blockIdx.z, b = z >> 3, h = z & 7;
    const int i0 = blockIdx.y * BM, j0 = blockIdx.x * BN;
    const int wm = (wid & 3) * 32;
    const int wn = (wid >> 2) * 64;

    const __nv_bfloat16* gAh = Qh + (size_t)(b * HD + h * DD) * NN_ + i0;
    const __nv_bfloat16* gAl = Ql + (size_t)(b * HD + h * DD) * NN_ + i0;
    const __nv_bfloat16* gBh = Kh + (size_t)(b * HD + h * DD) * NN_ + j0;
    const __nv_bfloat16* gBl = Kl + (size_t)(b * HD + h * DD) * NN_ + j0;

    const uint32_t sb = smem_u32(smem);

    const int lr = lane & 7, lg = lane >> 3;
    const int a_roff = lr + ((lg >> 1) & 1) * 8;
    const int a_coff = (lg & 1) * 8;
    const int b_roff = lr + (lg & 1) * 8;
    const int b_coff = ((lg >> 1) & 1) * 8;

    float acc[2][8][4] = {};

    const int iters = DD / BK;   // 8

    issue_stage_kt(sb, gAh, gAl, gBh, gBl, 0, tid);
    cp_commit();
    issue_stage_kt(sb + STAGE_KT * 2, gAh, gAl, gBh, gBl, BK, tid);
    cp_commit();

    for (int it = 0; it < iters; it++) {
        if (it + 1 < iters) cp_wait1(); else cp_wait0();
        __syncthreads();

        if (it + 2 < iters) {
            const uint32_t snxt = ((it + 2) % 3) * (STAGE_KT * 2);
            issue_stage_kt(sb + snxt, gAh, gAl, gBh, gBl, (it + 2) * BK, tid);
            cp_commit();
        }

        const uint32_t st = sb + (it % 3) * (STAGE_KT * 2);
#pragma unroll
        for (int kk = 0; kk < BK; kk += 16) {
            uint32_t ah[2][4], al[2][4];
#pragma unroll
            for (int mt = 0; mt < 2; mt++) {
                uint32_t ra = st + (uint32_t)(((kk + a_roff) * LDB_KT +
                                              wm + mt * 16 + a_coff) * 2);
                ldsm_x4_t(ah[mt], ra);
                ldsm_x4_t(al[mt], ra + TILE_KT * 2);
            }
#pragma unroll
            for (int g = 0; g < 4; g++) {
                uint32_t bh[4], bl[4];
                uint32_t rb = st + 2 * TILE_KT * 2 +
                              (uint32_t)(((kk + b_roff) * LDB_KT +
                                          wn + g * 16 + b_coff) * 2);
                ldsm_x4_t(bh, rb);
                ldsm_x4_t(bl, rb + TILE_KT * 2);
#pragma unroll
                for (int half = 0; half < 2; half++) {
                    const int u = half * 2;
                    const int nt = g * 2 + half;
#pragma unroll
                    for (int mt = 0; mt < 2; mt++) {
                        mma_bf16(acc[mt][nt], ah[mt], &bh[u]);
                        mma_bf16(acc[mt][nt], ah[mt], &bl[u]);
                        mma_bf16(acc[mt][nt], al[mt], &bh[u]);
                    }
                }
            }
        }
    }

#pragma unroll
    for (int mt = 0; mt < 2; mt++)
#pragma unroll
        for (int nt = 0; nt < 8; nt++) {
            int i = i0 + wm + mt * 16 + (lane >> 2);
            int j = j0 + wn + nt * 8 + 2 * (lane & 3);
            float* p0 = &S[((size_t)z * NN_ + i) * NN_ + j];
            float* p1 = &S[((size_t)z * NN_ + i + 8) * NN_ + j];
            *reinterpret_cast<float2*>(p0) = make_float2(acc[mt][nt][0], acc[mt][nt][1]);
            *reinterpret_cast<float2*>(p1) = make_float2(acc[mt][nt][2], acc[mt][nt][3]);
        }
}

// ===========================================================================
// attn_o: O = P V^T + fused epilogue. CTA 64x128, 8 warps of 32x32,
// 3-stage pipeline, register-capped. grid (2 dTiles, 16 iTiles, 32 z)
// ===========================================================================
__device__ __forceinline__ void issue_stage_o(
    uint32_t sbase,
    const __nv_bfloat16* gAh, const __nv_bfloat16* gAl,
    const __nv_bfloat16* gBh, const __nv_bfloat16* gBl,
    int k0, int tid)
{
    const int r = tid >> 2;          // 0..63
    const int q = tid & 3;
    const uint32_t so = (uint32_t)((r * LDA + q * 8) * 2);
    const size_t ga = (size_t)r * NN_ + k0 + q * 8;

    cp_async16(sbase + so, gAh + ga);
    cp_async16(sbase + TILE_O * 2 + so, gAl + ga);
    const uint32_t sb0 = sbase + (uint32_t)(OM * LDA * 2);
#pragma unroll
    for (int p = 0; p < 2; p++) {
        const int row = r + p * 64;
        const uint32_t sbo = sb0 + (uint32_t)((row * LDA + q * 8) * 2);
        const size_t gb = (size_t)row * NN_ + k0 + q * 8;
        cp_async16(sbo, gBh + gb);
        cp_async16(TILE_O * 2 + sbo, gBl + gb);
    }
}

__global__ void __launch_bounds__(256, 2) attn_o_kernel(
    const __nv_bfloat16* __restrict__ Ph, const __nv_bfloat16* __restrict__ Pl,
    const __nv_bfloat16* __restrict__ Vh, const __nv_bfloat16* __restrict__ Vl,
    const float* __restrict__ YP, const float* __restrict__ gamma,
    float* __restrict__ out)
{
    extern __shared__ char smem[];
    const int tid = threadIdx.x;
    const int lane = tid & 31, wid = tid >> 5;
    const int z = blockIdx.z, b = z >> 3, h = z & 7;
    const int i0 = blockIdx.y * OM, d0 = blockIdx.x * BN;
    const int wm = (wid & 1) * 32;
    const int wn = (wid >> 1) * 32;

    const __nv_bfloat16* gAh = Ph + ((size_t)z * NN_ + i0) * NN_;
    const __nv_bfloat16* gAl = Pl + ((size_t)z * NN_ + i0) * NN_;
    const __nv_bfloat16* gBh = Vh + ((size_t)b * HD + h * DD + d0) * NN_;
    const __nv_bfloat16* gBl = Vl + ((size_t)b * HD + h * DD + d0) * NN_;

    const uint32_t sb = smem_u32(smem);

    const int a_row = lane & 15;
    const int a_col = (lane >> 4) * 8;
    const int b_row = (lane & 7) + (lane >> 4) * 8;
    const int b_col = ((lane >> 3) & 1) * 8;

    float acc[2][4][4] = {};

    const int iters = NN_ / BK;   // 32

    issue_stage_o(sb, gAh, gAl, gBh, gBl, 0, tid);
    cp_commit();
    issue_stage_o(sb + STAGE_O * 2, gAh, gAl, gBh, gBl, BK, tid);
    cp_commit();

    for (int it = 0; it < iters; it++) {
        if (it + 1 < iters) cp_wait1(); else cp_wait0();
        __syncthreads();

        if (it + 2 < iters) {
            const uint32_t snxt = ((it + 2) % 3) * (STAGE_O * 2);
            issue_stage_o(sb + snxt, gAh, gAl, gBh, gBl, (it + 2) * BK, tid);
            cp_commit();
        }

        const uint32_t st = sb + (it % 3) * (STAGE_O * 2);
        const uint32_t stB = st + (uint32_t)(OM * LDA * 2);
#pragma unroll
        for (int kk = 0; kk < BK; kk += 16) {
            uint32_t ah[2][4], al[2][4];
#pragma unroll
            for (int mt = 0; mt < 2; mt++) {
                uint32_t ra = st + (uint32_t)(((wm + mt * 16 + a_row) * LDA + kk + a_col) * 2);
                ldsm_x4(ah[mt], ra);
                ldsm_x4(al[mt], ra + TILE_O * 2);
            }
#pragma unroll
            for (int g = 0; g < 2; g++) {
                uint32_t bh[4], bl[4];
                uint32_t rb = stB + (uint32_t)(((wn + g * 16 + b_row) * LDA + kk + b_col) * 2);
                ldsm_x4(bh, rb);
                ldsm_x4(bl, rb + TILE_O * 2);
#pragma unroll
                for (int half = 0; half < 2; half++) {
                    const int u = half * 2;
                    const int nt = g * 2 + half;
#pragma unroll
                    for (int mt = 0; mt < 2; mt++) {
                        mma_bf16(acc[mt][nt], ah[mt], &bh[u]);
                        mma_bf16(acc[mt][nt], ah[mt], &bl[u]);
                        mma_bf16(acc[mt][nt], al[mt], &bh[u]);
                    }
                }
            }
        }
    }

    const float g = gamma[h];
    const float inv1pg = 1.0f / (1.0f + g);
#pragma unroll
    for (int mt = 0; mt < 2; mt++)
#pragma unroll
        for (int nt = 0; nt < 4; nt++) {
            int i = i0 + wm + mt * 16 + (lane >> 2);
            int d = d0 + wn + nt * 8 + 2 * (lane & 3);
#pragma unroll
            for (int u = 0; u < 4; u++) {
                int dd = d + (u & 1);
                int ii = i + (u >> 1) * 8;
                float yp = YP[((size_t)b * CC + dd) * NN_ + ii];
                out[((size_t)b * HD + h * DD + dd) * NN_ + ii] =
                    (g * acc[mt][nt][u] + yp) * inv1pg;
            }
        }
}

// ===========================================================================
// Transpose+split both inputs: [B][C][N] fp32 -> [B][N][C] bf16 hi/lo
// ===========================================================================
__global__ void __launch_bounds__(256) transpose_split_in_kernel(
    const float* __restrict__ x, const float* __restrict__ y,
    __nv_bfloat16* __restrict__ xh, __nv_bfloat16* __restrict__ xl,
    __nv_bfloat16* __restrict__ yh, __nv_bfloat16* __restrict__ yl)
{
    __shared__ float t[32][33];
    int bz = blockIdx.z;
    const float* in;
    __nv_bfloat16 *oh, *ol;
    if (bz < BB) { in = x; oh = xh; ol = xl; }
    else { bz -= BB; in = y; oh = yh; ol = yl; }
    const int n0 = blockIdx.x * 32, c0 = blockIdx.y * 32;
    const int tx = threadIdx.x, ty = threadIdx.y;
    for (int r = ty; r < 32; r += 8)
        t[r][tx] = in[((size_t)bz * CC + c0 + r) * NN_ + n0 + tx];
    __syncthreads();
    for (int r = ty; r < 32; r += 8) {
        float v = t[tx][r];
        __nv_bfloat16 hi = __float2bfloat16(v);
        size_t o = ((size_t)bz * NN_ + n0 + r) * CC + c0 + tx;
        oh[o] = hi;
        ol[o] = __float2bfloat16(v - __bfloat162float(hi));
    }
}

// ===========================================================================
// Split all 4 weight matrices in one launch
// ===========================================================================
__global__ void __launch_bounds__(256) split_weights_kernel(
    const float* __restrict__ Wq, const float* __restrict__ Wk,
    const float* __restrict__ Wv, const float* __restrict__ Wp,
    __nv_bfloat16* __restrict__ Wqh, __nv_bfloat16* __restrict__ Wql,
    __nv_bfloat16* __restrict__ Wkh, __nv_bfloat16* __restrict__ Wkl,
    __nv_bfloat16* __restrict__ Wvh, __nv_bfloat16* __restrict__ Wvl,
    __nv_bfloat16* __restrict__ Wph, __nv_bfloat16* __restrict__ Wpl)
{
    const float* in;
    __nv_bfloat16 *oh, *ol;
    int n;
    switch (blockIdx.y) {
        case 0: in = Wq; oh = Wqh; ol = Wql; n = HD * CC; break;
        case 1: in = Wk; oh = Wkh; ol = Wkl; n = HD * CC; break;
        case 2: in = Wv; oh = Wvh; ol = Wvl; n = HD * CC; break;
        default: in = Wp; oh = Wph; ol = Wpl; n = CC * CC; break;
    }
    int i = blockIdx.x * 256 + threadIdx.x;
    if (i < n) {
        float v = in[i];
        __nv_bfloat16 hi = __float2bfloat16(v);
        oh[i] = hi;
        ol[i] = __float2bfloat16(v - __bfloat162float(hi));
    }
}

// ===========================================================================
// Warp-per-row softmax: grid 4096, block 256 (8 rows/block)
// ===========================================================================
__global__ void __launch_bounds__(256) softmax_kernel(
    const float* __restrict__ S,
    __nv_bfloat16* __restrict__ Ph, __nv_bfloat16* __restrict__ Pl)
{
    const int lane = threadIdx.x & 31;
    const size_t row = (size_t)blockIdx.x * 8 + (threadIdx.x >> 5);
    const float* r = S + row * NN_;

    float v[32];
    float mx = -INFINITY;
#pragma unroll
    for (int k = 0; k < 8; k++) {
        float4 f = *reinterpret_cast<const float4*>(r + k * 128 + lane * 4);
        v[k * 4 + 0] = f.x; v[k * 4 + 1] = f.y; v[k * 4 + 2] = f.z; v[k * 4 + 3] = f.w;
        mx = fmaxf(mx, fmaxf(fmaxf(f.x, f.y), fmaxf(f.z, f.w)));
    }
#pragma unroll
    for (int s = 16; s > 0; s >>= 1)
        mx = fmaxf(mx, __shfl_xor_sync(0xFFFFFFFFu, mx, s));

    float sum = 0.0f;
#pragma unroll
    for (int k = 0; k < 32; k++) { v[k] = __expf(v[k] - mx); sum += v[k]; }
#pragma unroll
    for (int s = 16; s > 0; s >>= 1)
        sum += __shfl_xor_sync(0xFFFFFFFFu, sum, s);
    const float inv = 1.0f / sum;

#pragma unroll
    for (int k = 0; k < 8; k++) {
        __nv_bfloat162 hp, lp;
        float p0 = v[k * 4 + 0] * inv, p1 = v[k * 4 + 1] * inv;
        float p2 = v[k * 4 + 2] * inv, p3 = v[k * 4 + 3] * inv;
        __nv_bfloat16 h0 = __float2bfloat16(p0), h1 = __float2bfloat16(p1);
        __nv_bfloat16 h2 = __float2bfloat16(p2), h3 = __float2bfloat16(p3);
        hp.x = h0; hp.y = h1;
        lp.x = __float2bfloat16(p0 - __bfloat162float(h0));
        lp.y = __float2bfloat16(p1 - __bfloat162float(h1));
        size_t o = row * NN_ + k * 128 + lane * 4;
        *reinterpret_cast<__nv_bfloat162*>(&Ph[o]) = hp;
        *reinterpret_cast<__nv_bfloat162*>(&Pl[o]) = lp;
        hp.x = h2; hp.y = h3;
        lp.x = __float2bfloat16(p2 - __bfloat162float(h2));
        lp.y = __float2bfloat16(p3 - __bfloat162float(h3));
        *reinterpret_cast<__nv_bfloat162*>(&Ph[o + 2]) = hp;
        *reinterpret_cast<__nv_bfloat162*>(&Pl[o + 2]) = lp;
    }
}

// ---------------------------------------------------------------------------
extern "C" void kernel_launch(void* const* d_in, const int* in_sizes, int n_in,
                              void* d_out, int out_size)
{
    const float* x     = (const float*)d_in[0];
    const float* y     = (const float*)d_in[1];
    const float* Wq    = (const float*)d_in[2];
    const float* bq    = (const float*)d_in[3];
    const float* Wk    = (const float*)d_in[4];
    const float* bk    = (const float*)d_in[5];
    const float* Wv    = (const float*)d_in[6];
    const float* bv    = (const float*)d_in[7];
    const float* Wp    = (const float*)d_in[8];
    const float* gamma = (const float*)d_in[9];
    float* out = (float*)d_out;

    float *YP, *S;
    __nv_bfloat16 *Wqh, *Wql, *Wkh, *Wkl, *Wvh, *Wvl, *Wph, *Wpl;
    __nv_bfloat16 *Xth, *Xtl, *Yth, *Ytl;
    __nv_bfloat16 *Qh, *Ql, *Kh, *Kl, *Vh, *Vl, *Ph, *Pl;
    cudaGetSymbolAddress((void**)&YP,  g_YP);
    cudaGetSymbolAddress((void**)&S,   g_S);
    cudaGetSymbolAddress((void**)&Wqh, g_Wqh);
    cudaGetSymbolAddress((void**)&Wql, g_Wql);
    cudaGetSymbolAddress((void**)&Wkh, g_Wkh);
    cudaGetSymbolAddress((void**)&Wkl, g_Wkl);
    cudaGetSymbolAddress((void**)&Wvh, g_Wvh);
    cudaGetSymbolAddress((void**)&Wvl, g_Wvl);
    cudaGetSymbolAddress((void**)&Wph, g_Wph);
    cudaGetSymbolAddress((void**)&Wpl, g_Wpl);
    cudaGetSymbolAddress((void**)&Xth, g_Xth);
    cudaGetSymbolAddress((void**)&Xtl, g_Xtl);
    cudaGetSymbolAddress((void**)&Yth, g_Yth);
    cudaGetSymbolAddress((void**)&Ytl, g_Ytl);
    cudaGetSymbolAddress((void**)&Qh,  g_Qh);
    cudaGetSymbolAddress((void**)&Ql,  g_Ql);
    cudaGetSymbolAddress((void**)&Kh,  g_Kh);
    cudaGetSymbolAddress((void**)&Kl,  g_Kl);
    cudaGetSymbolAddress((void**)&Vh,  g_Vh);
    cudaGetSymbolAddress((void**)&Vl,  g_Vl);
    cudaGetSymbolAddress((void**)&Ph,  g_Ph);
    cudaGetSymbolAddress((void**)&Pl,  g_Pl);

    cudaFuncSetAttribute(proj_all_kernel, cudaFuncAttributeMaxDynamicSharedMemorySize, SMEM_BYTES);
    cudaFuncSetAttribute(attn_s_kernel, cudaFuncAttributeMaxDynamicSharedMemorySize, SMEM_S_BYTES);
    cudaFuncSetAttribute(attn_o_kernel, cudaFuncAttributeMaxDynamicSharedMemorySize, SMEM_O_BYTES);

    dim3 t(256);

    // Weight splits (1 launch)
    split_weights_kernel<<<dim3((HD * CC + 255) / 256, 4), t>>>(
        Wq, Wk, Wv, Wp, Wqh, Wql, Wkh, Wkl, Wvh, Wvl, Wph, Wpl);

    // Input transposes+splits (1 launch)
    transpose_split_in_kernel<<<dim3(32, 8, 2 * BB), dim3(32, 8)>>>(
        x, y, Xth, Xtl, Yth, Ytl);

    // All projections (Q/K/V/YP) in 1 launch, 1600 CTAs
    proj_all_kernel<<<dim3(8, 50, BB), t, SMEM_BYTES>>>(
        Wqh, Wql, Wkh, Wkl, Wvh, Wvl, Wph, Wpl,
        Xth, Xtl, Yth, Ytl, bq, bk, bv,
        Qh, Ql, Kh, Kl, Vh, Vl, YP);

    // S = Q^T K (3-stage pipeline, reg-capped)
    attn_s_kernel<<<dim3(8, 8, ZZ), t, SMEM_S_BYTES>>>(Qh, Ql, Kh, Kl, S);

    // softmax -> P hi/lo
    softmax_kernel<<<ZZ * NN_ / 8, t>>>(S, Ph, Pl);

    // O = P V^T + epilogue (3-stage pipeline, reg-capped)
    attn_o_kernel<<<dim3(2, 16, ZZ), t, SMEM_O_BYTES>>>(Ph, Pl, Vh, Vl, YP, gamma, out);
}

// round 17
// speedup vs baseline: 1.7711x; 1.7711x over previous
#include <cuda_runtime.h>
#include <cuda_bf16.h>
#include <cuda_fp16.h>
#include <math.h>
#include <stdint.h>

// Problem constants
#define BB 4
#define CC 256
#define NN_ 1024
#define HH 8
#define DD 256
#define HD 2048
#define ZZ 32   // B*H

// GEMM tiling: CTA 128x128, 8 warps of 32x64 (proven config)
#define BM 128
#define BN 128
#define BK 32
#define LDA 40                 // padded row length (16-bit elems) = 80 B
#define TILE_E (128 * LDA)
#define STAGE_E (4 * TILE_E)
#define SMEM_BYTES (2 * STAGE_E * 2)

// attn_o tiling: CTA 64x128, 8 warps of 32x32, 2-stage.
// Stage: Ah(64 rows) + Al(64 rows) + Bh(128 rows), rows of LDA halves.
#define OM 64
#define OA_E (OM * LDA)              // one A tile
#define STAGE_O (2 * OA_E + 2 * OA_E * 2)   // = 256*LDA elems (Ah,Al,Bh128)
#define SMEM_O_BYTES (2 * STAGE_O * 2)

// k-major tiling (attn_s), 2-stage. Stage: Ah + Al + Bh (3 tiles)
#define LDB_KT 136
#define TILE_KT (32 * LDB_KT)
#define STAGE_KT (3 * TILE_KT)
#define SMEM_S_BYTES (2 * STAGE_KT * 2)

// ---------------- scratch ----------------------------------------------------
__device__ __align__(256) float g_YP[(size_t)BB * CC * NN_];
__device__ __align__(256) float g_S[(size_t)ZZ * NN_ * NN_];

__device__ __align__(256) __nv_bfloat16 g_Wqh[(size_t)HD * CC];
__device__ __align__(256) __nv_bfloat16 g_Wql[(size_t)HD * CC];
__device__ __align__(256) __nv_bfloat16 g_Wkh[(size_t)HD * CC];
__device__ __align__(256) __nv_bfloat16 g_Wkl[(size_t)HD * CC];
__device__ __align__(256) __nv_bfloat16 g_Wvh[(size_t)HD * CC];
__device__ __align__(256) __nv_bfloat16 g_Wvl[(size_t)HD * CC];
__device__ __align__(256) __nv_bfloat16 g_Wph[(size_t)CC * CC];
__device__ __align__(256) __nv_bfloat16 g_Wpl[(size_t)CC * CC];

__device__ __align__(256) __nv_bfloat16 g_Xth[(size_t)BB * NN_ * CC];
__device__ __align__(256) __nv_bfloat16 g_Xtl[(size_t)BB * NN_ * CC];
__device__ __align__(256) __nv_bfloat16 g_Yth[(size_t)BB * NN_ * CC];
__device__ __align__(256) __nv_bfloat16 g_Ytl[(size_t)BB * NN_ * CC];

// attention operands (fp16)
__device__ __align__(256) __half g_Qh[(size_t)BB * HD * NN_];
__device__ __align__(256) __half g_Ql[(size_t)BB * HD * NN_];
__device__ __align__(256) __half g_Kh[(size_t)BB * HD * NN_];
__device__ __align__(256) __half g_Vh[(size_t)BB * HD * NN_];
__device__ __align__(256) __half g_Ph[(size_t)ZZ * NN_ * NN_];
__device__ __align__(256) __half g_Pl[(size_t)ZZ * NN_ * NN_];

// ---------------- helpers ----------------------------------------------------
__device__ __forceinline__ uint32_t smem_u32(const void* p) {
    uint32_t a;
    asm("{ .reg .u64 t; cvta.to.shared.u64 t, %1; cvt.u32.u64 %0, t; }"
        : "=r"(a) : "l"(p));
    return a;
}
__device__ __forceinline__ void ldsm_x4(uint32_t* r, uint32_t addr) {
    asm volatile("ldmatrix.sync.aligned.m8n8.x4.shared.b16 {%0,%1,%2,%3}, [%4];"
                 : "=r"(r[0]), "=r"(r[1]), "=r"(r[2]), "=r"(r[3]) : "r"(addr));
}
__device__ __forceinline__ void ldsm_x4_t(uint32_t* r, uint32_t addr) {
    asm volatile("ldmatrix.sync.aligned.m8n8.x4.trans.shared.b16 {%0,%1,%2,%3}, [%4];"
                 : "=r"(r[0]), "=r"(r[1]), "=r"(r[2]), "=r"(r[3]) : "r"(addr));
}
__device__ __forceinline__ void mma_bf16(float* c, const uint32_t* a, const uint32_t* b) {
    asm volatile(
        "mma.sync.aligned.m16n8k16.row.col.f32.bf16.bf16.f32 "
        "{%0,%1,%2,%3}, {%4,%5,%6,%7}, {%8,%9}, {%0,%1,%2,%3};"
        : "+f"(c[0]), "+f"(c[1]), "+f"(c[2]), "+f"(c[3])
        : "r"(a[0]), "r"(a[1]), "r"(a[2]), "r"(a[3]), "r"(b[0]), "r"(b[1]));
}
__device__ __forceinline__ void mma_f16(float* c, const uint32_t* a, const uint32_t* b) {
    asm volatile(
        "mma.sync.aligned.m16n8k16.row.col.f32.f16.f16.f32 "
        "{%0,%1,%2,%3}, {%4,%5,%6,%7}, {%8,%9}, {%0,%1,%2,%3};"
        : "+f"(c[0]), "+f"(c[1]), "+f"(c[2]), "+f"(c[3])
        : "r"(a[0]), "r"(a[1]), "r"(a[2]), "r"(a[3]), "r"(b[0]), "r"(b[1]));
}
__device__ __forceinline__ void cp_async16(uint32_t sm, const void* g) {
    asm volatile("cp.async.cg.shared.global [%0], [%1], 16;" :: "r"(sm), "l"(g));
}
__device__ __forceinline__ void cp_commit() {
    asm volatile("cp.async.commit_group;" ::: "memory");
}
__device__ __forceinline__ void cp_wait1() {
    asm volatile("cp.async.wait_group 1;" ::: "memory");
}
__device__ __forceinline__ void cp_wait0() {
    asm volatile("cp.async.wait_group 0;" ::: "memory");
}

// ===========================================================================
// j-major mainloop (proj, bf16 3-term): 256 threads, 8 warps of 32x64, 2-stage
// ===========================================================================
__device__ __forceinline__ void issue_stage(
    uint32_t sbase,
    const __nv_bfloat16* gAh, const __nv_bfloat16* gAl, size_t strideA,
    const __nv_bfloat16* gBh, const __nv_bfloat16* gBl, size_t strideB,
    int k0, int tid)
{
    const int r = tid >> 2;
    const int q = tid & 3;
    const uint32_t so = (uint32_t)((r * LDA + q * 8) * 2);
    const uint32_t so2 = (uint32_t)(((r + 64) * LDA + q * 8) * 2);
    const size_t go = (size_t)r * strideA + k0 + q * 8;
    const size_t go2 = (size_t)(r + 64) * strideA + k0 + q * 8;
    const size_t gb = (size_t)r * strideB + k0 + q * 8;
    const size_t gb2 = (size_t)(r + 64) * strideB + k0 + q * 8;

    cp_async16(sbase + so, gAh + go);
    cp_async16(sbase + so2, gAh + go2);
    cp_async16(sbase + TILE_E * 2 + so, gAl + go);
    cp_async16(sbase + TILE_E * 2 + so2, gAl + go2);
    cp_async16(sbase + 2 * TILE_E * 2 + so, gBh + gb);
    cp_async16(sbase + 2 * TILE_E * 2 + so2, gBh + gb2);
    cp_async16(sbase + 3 * TILE_E * 2 + so, gBl + gb);
    cp_async16(sbase + 3 * TILE_E * 2 + so2, gBl + gb2);
}

__device__ __forceinline__ void mma_mainloop(
    const __nv_bfloat16* __restrict__ gAh, const __nv_bfloat16* __restrict__ gAl,
    size_t strideA,
    const __nv_bfloat16* __restrict__ gBh, const __nv_bfloat16* __restrict__ gBl,
    size_t strideB,
    int KTOT, char* smem, float acc[2][8][4])
{
    const int tid = threadIdx.x;
    const int lane = tid & 31, wid = tid >> 5;
    const int wm = (wid & 3) * 32;
    const int wn = (wid >> 2) * 64;

    const uint32_t sb = smem_u32(smem);

    const int a_row = lane & 15;
    const int a_col = (lane >> 4) * 8;
    const int b_row = (lane & 7) + (lane >> 4) * 8;
    const int b_col = ((lane >> 3) & 1) * 8;

    const int iters = KTOT / BK;

    issue_stage(sb, gAh, gAl, strideA, gBh, gBl, strideB, 0, tid);
    cp_commit();

    for (int it = 0; it < iters; it++) {
        if (it + 1 < iters) {
            issue_stage(sb + ((it + 1) & 1) * STAGE_E * 2,
                        gAh, gAl, strideA, gBh, gBl, strideB, (it + 1) * BK, tid);
            cp_commit();
            cp_wait1();
        } else {
            cp_wait0();
        }
        __syncthreads();

        const uint32_t st = sb + (it & 1) * STAGE_E * 2;
#pragma unroll
        for (int kk = 0; kk < BK; kk += 16) {
            uint32_t ah[2][4], al[2][4];
#pragma unroll
            for (int mt = 0; mt < 2; mt++) {
                uint32_t ra = st + (uint32_t)(((wm + mt * 16 + a_row) * LDA + kk + a_col) * 2);
                ldsm_x4(ah[mt], ra);
                ldsm_x4(al[mt], ra + TILE_E * 2);
            }
#pragma unroll
            for (int g = 0; g < 4; g++) {
                uint32_t bh[4], bl[4];
                uint32_t rb = st + 2 * TILE_E * 2 +
                              (uint32_t)(((wn + g * 16 + b_row) * LDA + kk + b_col) * 2);
                ldsm_x4(bh, rb);
                ldsm_x4(bl, rb + TILE_E * 2);
#pragma unroll
                for (int half = 0; half < 2; half++) {
                    const int u = half * 2;
                    const int nt = g * 2 + half;
#pragma unroll
                    for (int mt = 0; mt < 2; mt++) {
                        mma_bf16(acc[mt][nt], ah[mt], &bh[u]);
                        mma_bf16(acc[mt][nt], ah[mt], &bl[u]);
                        mma_bf16(acc[mt][nt], al[mt], &bh[u]);
                    }
                }
            }
        }
        __syncthreads();
    }
}

// ===========================================================================
// Merged projection: grid (8, 50, B). y: [0,16)->Q hi/lo, [16,32)->K single,
// [32,48)->V single, [48,50)->Wp fp32.
// ===========================================================================
__global__ void __launch_bounds__(256) proj_all_kernel(
    const __nv_bfloat16* __restrict__ Wqh, const __nv_bfloat16* __restrict__ Wql,
    const __nv_bfloat16* __restrict__ Wkh, const __nv_bfloat16* __restrict__ Wkl,
    const __nv_bfloat16* __restrict__ Wvh, const __nv_bfloat16* __restrict__ Wvl,
    const __nv_bfloat16* __restrict__ Wph, const __nv_bfloat16* __restrict__ Wpl,
    const __nv_bfloat16* __restrict__ Xh, const __nv_bfloat16* __restrict__ Xl,
    const __nv_bfloat16* __restrict__ Yh, const __nv_bfloat16* __restrict__ Yl,
    const float* __restrict__ bq, const float* __restrict__ bk,
    const float* __restrict__ bv,
    __half* __restrict__ Qh, __half* __restrict__ Ql,
    __half* __restrict__ Kh, __half* __restrict__ Vh,
    float* __restrict__ YP)
{
    extern __shared__ char smem[];
    const int z = blockIdx.z;
    const int yb = blockIdx.y;
    const int n0 = blockIdx.x * BN;

    const __nv_bfloat16 *Wh, *Wl, *Ih, *Il;
    const float* bias = nullptr;
    __half *outH = nullptr, *outL = nullptr;
    float* outF = nullptr;
    int m0;
    if (yb < 16)      { Wh = Wqh; Wl = Wql; Ih = Xh; Il = Xl; bias = bq; outH = Qh; outL = Ql; m0 = yb * BM; }
    else if (yb < 32) { Wh = Wkh; Wl = Wkl; Ih = Xh; Il = Xl; bias = bk; outH = Kh; m0 = (yb - 16) * BM; }
    else if (yb < 48) { Wh = Wvh; Wl = Wvl; Ih = Yh; Il = Yl; bias = bv; outH = Vh; m0 = (yb - 32) * BM; }
    else              { Wh = Wph; Wl = Wpl; Ih = Yh; Il = Yl; outF = YP; m0 = (yb - 48) * BM; }

    float acc[2][8][4] = {};
    mma_mainloop(Wh + (size_t)m0 * CC, Wl + (size_t)m0 * CC, CC,
                 Ih + ((size_t)z * NN_ + n0) * CC, Il + ((size_t)z * NN_ + n0) * CC, CC,
                 CC, smem, acc);

    const int lane = threadIdx.x & 31, wid = threadIdx.x >> 5;
    const int wm = (wid & 3) * 32, wn = (wid >> 2) * 64;
#pragma unroll
    for (int mt = 0; mt < 2; mt++)
#pragma unroll
        for (int nt = 0; nt < 8; nt++) {
            int m = m0 + wm + mt * 16 + (lane >> 2);
            int n = n0 + wn + nt * 8 + 2 * (lane & 3);
            if (outF) {
                *reinterpret_cast<float2*>(&outF[((size_t)z * CC + m) * NN_ + n]) =
                    make_float2(acc[mt][nt][0], acc[mt][nt][1]);
                *reinterpret_cast<float2*>(&outF[((size_t)z * CC + m + 8) * NN_ + n]) =
                    make_float2(acc[mt][nt][2], acc[mt][nt][3]);
            } else {
                float b0 = bias[m], b1 = bias[m + 8];
                float v00 = acc[mt][nt][0] + b0, v01 = acc[mt][nt][1] + b0;
                float v10 = acc[mt][nt][2] + b1, v11 = acc[mt][nt][3] + b1;
                __half h00 = __float2half(v00), h01 = __float2half(v01);
                __half h10 = __float2half(v10), h11 = __float2half(v11);
                __half2 hp0; hp0.x = h00; hp0.y = h01;
                __half2 hp1; hp1.x = h10; hp1.y = h11;
                *reinterpret_cast<__half2*>(&outH[((size_t)z * HD + m) * NN_ + n]) = hp0;
                *reinterpret_cast<__half2*>(&outH[((size_t)z * HD + m + 8) * NN_ + n]) = hp1;
                if (outL) {
                    __half2 lp0, lp1;
                    lp0.x = __float2half(v00 - __half2float(h00));
                    lp0.y = __float2half(v01 - __half2float(h01));
                    lp1.x = __float2half(v10 - __half2float(h10));
                    lp1.y = __float2half(v11 - __half2float(h11));
                    *reinterpret_cast<__half2*>(&outL[((size_t)z * HD + m) * NN_ + n]) = lp0;
                    *reinterpret_cast<__half2*>(&outL[((size_t)z * HD + m + 8) * NN_ + n]) = lp1;
                }
            }
        }
}

// ===========================================================================
// attn_s: S = Q^T K, fp16 asymmetric (Q hi/lo, K single). k-major, trans ldsm,
// 2-stage. grid (8, 8, 32)
// ===========================================================================
__device__ __forceinline__ void issue_stage_kt(
    uint32_t sbase,
    const __half* gAh, const __half* gAl, const __half* gBh,
    int k0, int tid)
{
    const int r = tid >> 4;
    const int c = tid & 15;
#pragma unroll
    for (int p = 0; p < 2; p++) {
        const int row = r + p * 16;
        const uint32_t so = (uint32_t)((row * LDB_KT + c * 8) * 2);
        const size_t go = (size_t)(k0 + row) * NN_ + c * 8;
        cp_async16(sbase + so, gAh + go);
        cp_async16(sbase + TILE_KT * 2 + so, gAl + go);
        cp_async16(sbase + 2 * TILE_KT * 2 + so, gBh + go);
    }
}

__global__ void __launch_bounds__(256) attn_s_kernel(
    const __half* __restrict__ Qh, const __half* __restrict__ Ql,
    const __half* __restrict__ Kh,
    float* __restrict__ S)
{
    extern __shared__ char smem[];
    const int tid = threadIdx.x;
    const int lane = tid & 31, wid = tid >> 5;
    const int z = blockIdx.z, b = z >> 3, h = z & 7;
    const int i0 = blockIdx.y * BM, j0 = blockIdx.x * BN;
    const int wm = (wid & 3) * 32;
    const int wn = (wid >> 2) * 64;

    const __half* gAh = Qh + (size_t)(b * HD + h * DD) * NN_ + i0;
    const __half* gAl = Ql + (size_t)(b * HD + h * DD) * NN_ + i0;
    const __half* gBh = Kh + (size_t)(b * HD + h * DD) * NN_ + j0;

    const uint32_t sb = smem_u32(smem);

    const int lr = lane & 7, lg = lane >> 3;
    const int a_roff = lr + ((lg >> 1) & 1) * 8;
    const int a_coff = (lg & 1) * 8;
    const int b_roff = lr + (lg & 1) * 8;
    const int b_coff = ((lg >> 1) & 1) * 8;

    float acc[2][8][4] = {};

    const int iters = DD / BK;   // 8

    issue_stage_kt(sb, gAh, gAl, gBh, 0, tid);
    cp_commit();

    for (int it = 0; it < iters; it++) {
        if (it + 1 < iters) {
            issue_stage_kt(sb + ((it + 1) & 1) * STAGE_KT * 2,
                           gAh, gAl, gBh, (it + 1) * BK, tid);
            cp_commit();
            cp_wait1();
        } else {
            cp_wait0();
        }
        __syncthreads();

        const uint32_t st = sb + (it & 1) * STAGE_KT * 2;
#pragma unroll
        for (int kk = 0; kk < BK; kk += 16) {
            uint32_t ah[2][4], al[2][4];
#pragma unroll
            for (int mt = 0; mt < 2; mt++) {
                uint32_t ra = st + (uint32_t)(((kk + a_roff) * LDB_KT +
                                              wm + mt * 16 + a_coff) * 2);
                ldsm_x4_t(ah[mt], ra);
                ldsm_x4_t(al[mt], ra + TILE_KT * 2);
            }
#pragma unroll
            for (int g = 0; g < 4; g++) {
                uint32_t bh[4];
                uint32_t rb = st + 2 * TILE_KT * 2 +
                              (uint32_t)(((kk + b_roff) * LDB_KT +
                                          wn + g * 16 + b_coff) * 2);
                ldsm_x4_t(bh, rb);
#pragma unroll
                for (int half = 0; half < 2; half++) {
                    const int u = half * 2;
                    const int nt = g * 2 + half;
#pragma unroll
                    for (int mt = 0; mt < 2; mt++) {
                        mma_f16(acc[mt][nt], ah[mt], &bh[u]);
                        mma_f16(acc[mt][nt], al[mt], &bh[u]);
                    }
                }
            }
        }
        __syncthreads();
    }

#pragma unroll
    for (int mt = 0; mt < 2; mt++)
#pragma unroll
        for (int nt = 0; nt < 8; nt++) {
            int i = i0 + wm + mt * 16 + (lane >> 2);
            int j = j0 + wn + nt * 8 + 2 * (lane & 3);
            float* p0 = &S[((size_t)z * NN_ + i) * NN_ + j];
            float* p1 = &S[((size_t)z * NN_ + i + 8) * NN_ + j];
            *reinterpret_cast<float2*>(p0) = make_float2(acc[mt][nt][0], acc[mt][nt][1]);
            *reinterpret_cast<float2*>(p1) = make_float2(acc[mt][nt][2], acc[mt][nt][3]);
        }
}

// ===========================================================================
// attn_o: O = P V^T + fused epilogue, fp16 asymmetric (P hi/lo, V single).
// CTA 64x128, 8 warps of 32x32, 2-stage. grid (2, 16, 32)
// Stage layout: Ah(64 rows) | Al(64 rows) | Bh(128 rows)
// ===========================================================================
__device__ __forceinline__ void issue_stage_o(
    uint32_t sbase,
    const __half* gAh, const __half* gAl, const __half* gBh,
    int k0, int tid)
{
    const int r = tid >> 2;          // 0..63
    const int q = tid & 3;
    const uint32_t so = (uint32_t)((r * LDA + q * 8) * 2);
    const size_t ga = (size_t)r * NN_ + k0 + q * 8;

    cp_async16(sbase + so, gAh + ga);                       // Ah
    cp_async16(sbase + OA_E * 2 + so, gAl + ga);            // Al
    const uint32_t sb0 = sbase + (uint32_t)(2 * OA_E * 2);  // Bh base
#pragma unroll
    for (int p = 0; p < 2; p++) {
        const int row = r + p * 64;
        const uint32_t sbo = sb0 + (uint32_t)((row * LDA + q * 8) * 2);
        const size_t gb = (size_t)row * NN_ + k0 + q * 8;
        cp_async16(sbo, gBh + gb);
    }
}

__global__ void __launch_bounds__(256) attn_o_kernel(
    const __half* __restrict__ Ph, const __half* __restrict__ Pl,
    const __half* __restrict__ Vh,
    const float* __restrict__ YP, const float* __restrict__ gamma,
    float* __restrict__ out)
{
    extern __shared__ char smem[];
    const int tid = threadIdx.x;
    const int lane = tid & 31, wid = tid >> 5;
    const int z = blockIdx.z, b = z >> 3, h = z & 7;
    const int i0 = blockIdx.y * OM, d0 = blockIdx.x * BN;
    const int wm = (wid & 1) * 32;
    const int wn = (wid >> 1) * 32;

    const __half* gAh = Ph + ((size_t)z * NN_ + i0) * NN_;
    const __half* gAl = Pl + ((size_t)z * NN_ + i0) * NN_;
    const __half* gBh = Vh + ((size_t)b * HD + h * DD + d0) * NN_;

    const uint32_t sb = smem_u32(smem);

    const int a_row = lane & 15;
    const int a_col = (lane >> 4) * 8;
    const int b_row = (lane & 7) + (lane >> 4) * 8;
    const int b_col = ((lane >> 3) & 1) * 8;

    float acc[2][4][4] = {};

    const int iters = NN_ / BK;   // 32

    issue_stage_o(sb, gAh, gAl, gBh, 0, tid);
    cp_commit();

    for (int it = 0; it < iters; it++) {
        if (it + 1 < iters) {
            issue_stage_o(sb + ((it + 1) & 1) * STAGE_O * 2,
                          gAh, gAl, gBh, (it + 1) * BK, tid);
            cp_commit();
            cp_wait1();
        } else {
            cp_wait0();
        }
        __syncthreads();

        const uint32_t st = sb + (it & 1) * STAGE_O * 2;
        const uint32_t stB = st + (uint32_t)(2 * OA_E * 2);
#pragma unroll
        for (int kk = 0; kk < BK; kk += 16) {
            uint32_t ah[2][4], al[2][4];
#pragma unroll
            for (int mt = 0; mt < 2; mt++) {
                uint32_t ra = st + (uint32_t)(((wm + mt * 16 + a_row) * LDA + kk + a_col) * 2);
                ldsm_x4(ah[mt], ra);
                ldsm_x4(al[mt], ra + OA_E * 2);
            }
#pragma unroll
            for (int g = 0; g < 2; g++) {
                uint32_t bh[4];
                uint32_t rb = stB + (uint32_t)(((wn + g * 16 + b_row) * LDA + kk + b_col) * 2);
                ldsm_x4(bh, rb);
#pragma unroll
                for (int half = 0; half < 2; half++) {
                    const int u = half * 2;
                    const int nt = g * 2 + half;
#pragma unroll
                    for (int mt = 0; mt < 2; mt++) {
                        mma_f16(acc[mt][nt], ah[mt], &bh[u]);
                        mma_f16(acc[mt][nt], al[mt], &bh[u]);
                    }
                }
            }
        }
        __syncthreads();
    }

    const float g = gamma[h];
    const float inv1pg = 1.0f / (1.0f + g);
#pragma unroll
    for (int mt = 0; mt < 2; mt++)
#pragma unroll
        for (int nt = 0; nt < 4; nt++) {
            int i = i0 + wm + mt * 16 + (lane >> 2);
            int d = d0 + wn + nt * 8 + 2 * (lane & 3);
#pragma unroll
            for (int u = 0; u < 4; u++) {
                int dd = d + (u & 1);
                int ii = i + (u >> 1) * 8;
                float yp = YP[((size_t)b * CC + dd) * NN_ + ii];
                out[((size_t)b * HD + h * DD + dd) * NN_ + ii] =
                    (g * acc[mt][nt][u] + yp) * inv1pg;
            }
        }
}

// ===========================================================================
// Transpose+split both inputs: [B][C][N] fp32 -> [B][N][C] bf16 hi/lo
// ===========================================================================
__global__ void __launch_bounds__(256) transpose_split_in_kernel(
    const float* __restrict__ x, const float* __restrict__ y,
    __nv_bfloat16* __restrict__ xh, __nv_bfloat16* __restrict__ xl,
    __nv_bfloat16* __restrict__ yh, __nv_bfloat16* __restrict__ yl)
{
    __shared__ float t[32][33];
    int bz = blockIdx.z;
    const float* in;
    __nv_bfloat16 *oh, *ol;
    if (bz < BB) { in = x; oh = xh; ol = xl; }
    else { bz -= BB; in = y; oh = yh; ol = yl; }
    const int n0 = blockIdx.x * 32, c0 = blockIdx.y * 32;
    const int tx = threadIdx.x, ty = threadIdx.y;
    for (int r = ty; r < 32; r += 8)
        t[r][tx] = in[((size_t)bz * CC + c0 + r) * NN_ + n0 + tx];
    __syncthreads();
    for (int r = ty; r < 32; r += 8) {
        float v = t[tx][r];
        __nv_bfloat16 hi = __float2bfloat16(v);
        size_t o = ((size_t)bz * NN_ + n0 + r) * CC + c0 + tx;
        oh[o] = hi;
        ol[o] = __float2bfloat16(v - __bfloat162float(hi));
    }
}

// ===========================================================================
// Split all 4 weight matrices in one launch
// ===========================================================================
__global__ void __launch_bounds__(256) split_weights_kernel(
    const float* __restrict__ Wq, const float* __restrict__ Wk,
    const float* __restrict__ Wv, const float* __restrict__ Wp,
    __nv_bfloat16* __restrict__ Wqh, __nv_bfloat16* __restrict__ Wql,
    __nv_bfloat16* __restrict__ Wkh, __nv_bfloat16* __restrict__ Wkl,
    __nv_bfloat16* __restrict__ Wvh, __nv_bfloat16* __restrict__ Wvl,
    __nv_bfloat16* __restrict__ Wph, __nv_bfloat16* __restrict__ Wpl)
{
    const float* in;
    __nv_bfloat16 *oh, *ol;
    int n;
    switch (blockIdx.y) {
        case 0: in = Wq; oh = Wqh; ol = Wql; n = HD * CC; break;
        case 1: in = Wk; oh = Wkh; ol = Wkl; n = HD * CC; break;
        case 2: in = Wv; oh = Wvh; ol = Wvl; n = HD * CC; break;
        default: in = Wp; oh = Wph; ol = Wpl; n = CC * CC; break;
    }
    int i = blockIdx.x * 256 + threadIdx.x;
    if (i < n) {
        float v = in[i];
        __nv_bfloat16 hi = __float2bfloat16(v);
        oh[i] = hi;
        ol[i] = __float2bfloat16(v - __bfloat162float(hi));
    }
}

// ===========================================================================
// Warp-per-row softmax: grid 4096, block 256 (8 rows/block), emits fp16 hi/lo
// ===========================================================================
__global__ void __launch_bounds__(256) softmax_kernel(
    const float* __restrict__ S,
    __half* __restrict__ Ph, __half* __restrict__ Pl)
{
    const int lane = threadIdx.x & 31;
    const size_t row = (size_t)blockIdx.x * 8 + (threadIdx.x >> 5);
    const float* r = S + row * NN_;

    float v[32];
    float mx = -INFINITY;
#pragma unroll
    for (int k = 0; k < 8; k++) {
        float4 f = *reinterpret_cast<const float4*>(r + k * 128 + lane * 4);
        v[k * 4 + 0] = f.x; v[k * 4 + 1] = f.y; v[k * 4 + 2] = f.z; v[k * 4 + 3] = f.w;
        mx = fmaxf(mx, fmaxf(fmaxf(f.x, f.y), fmaxf(f.z, f.w)));
    }
#pragma unroll
    for (int s = 16; s > 0; s >>= 1)
        mx = fmaxf(mx, __shfl_xor_sync(0xFFFFFFFFu, mx, s));

    float sum = 0.0f;
#pragma unroll
    for (int k = 0; k < 32; k++) { v[k] = __expf(v[k] - mx); sum += v[k]; }
#pragma unroll
    for (int s = 16; s > 0; s >>= 1)
        sum += __shfl_xor_sync(0xFFFFFFFFu, sum, s);
    const float inv = 1.0f / sum;

#pragma unroll
    for (int k = 0; k < 8; k++) {
        __half2 hp, lp;
        float p0 = v[k * 4 + 0] * inv, p1 = v[k * 4 + 1] * inv;
        float p2 = v[k * 4 + 2] * inv, p3 = v[k * 4 + 3] * inv;
        __half h0 = __float2half(p0), h1 = __float2half(p1);
        __half h2 = __float2half(p2), h3 = __float2half(p3);
        hp.x = h0; hp.y = h1;
        lp.x = __float2half(p0 - __half2float(h0));
        lp.y = __float2half(p1 - __half2float(h1));
        size_t o = row * NN_ + k * 128 + lane * 4;
        *reinterpret_cast<__half2*>(&Ph[o]) = hp;
        *reinterpret_cast<__half2*>(&Pl[o]) = lp;
        hp.x = h2; hp.y = h3;
        lp.x = __float2half(p2 - __half2float(h2));
        lp.y = __float2half(p3 - __half2float(h3));
        *reinterpret_cast<__half2*>(&Ph[o + 2]) = hp;
        *reinterpret_cast<__half2*>(&Pl[o + 2]) = lp;
    }
}

// ---------------------------------------------------------------------------
extern "C" void kernel_launch(void* const* d_in, const int* in_sizes, int n_in,
                              void* d_out, int out_size)
{
    const float* x     = (const float*)d_in[0];
    const float* y     = (const float*)d_in[1];
    const float* Wq    = (const float*)d_in[2];
    const float* bq    = (const float*)d_in[3];
    const float* Wk    = (const float*)d_in[4];
    const float* bk    = (const float*)d_in[5];
    const float* Wv    = (const float*)d_in[6];
    const float* bv    = (const float*)d_in[7];
    const float* Wp    = (const float*)d_in[8];
    const float* gamma = (const float*)d_in[9];
    float* out = (float*)d_out;

    float *YP, *S;
    __nv_bfloat16 *Wqh, *Wql, *Wkh, *Wkl, *Wvh, *Wvl, *Wph, *Wpl;
    __nv_bfloat16 *Xth, *Xtl, *Yth, *Ytl;
    __half *Qh, *Ql, *Kh, *Vh, *Ph, *Pl;
    cudaGetSymbolAddress((void**)&YP,  g_YP);
    cudaGetSymbolAddress((void**)&S,   g_S);
    cudaGetSymbolAddress((void**)&Wqh, g_Wqh);
    cudaGetSymbolAddress((void**)&Wql, g_Wql);
    cudaGetSymbolAddress((void**)&Wkh, g_Wkh);
    cudaGetSymbolAddress((void**)&Wkl, g_Wkl);
    cudaGetSymbolAddress((void**)&Wvh, g_Wvh);
    cudaGetSymbolAddress((void**)&Wvl, g_Wvl);
    cudaGetSymbolAddress((void**)&Wph, g_Wph);
    cudaGetSymbolAddress((void**)&Wpl, g_Wpl);
    cudaGetSymbolAddress((void**)&Xth, g_Xth);
    cudaGetSymbolAddress((void**)&Xtl, g_Xtl);
    cudaGetSymbolAddress((void**)&Yth, g_Yth);
    cudaGetSymbolAddress((void**)&Ytl, g_Ytl);
    cudaGetSymbolAddress((void**)&Qh,  g_Qh);
    cudaGetSymbolAddress((void**)&Ql,  g_Ql);
    cudaGetSymbolAddress((void**)&Kh,  g_Kh);
    cudaGetSymbolAddress((void**)&Vh,  g_Vh);
    cudaGetSymbolAddress((void**)&Ph,  g_Ph);
    cudaGetSymbolAddress((void**)&Pl,  g_Pl);

    cudaFuncSetAttribute(proj_all_kernel, cudaFuncAttributeMaxDynamicSharedMemorySize, SMEM_BYTES);
    cudaFuncSetAttribute(attn_s_kernel, cudaFuncAttributeMaxDynamicSharedMemorySize, SMEM_S_BYTES);
    cudaFuncSetAttribute(attn_o_kernel, cudaFuncAttributeMaxDynamicSharedMemorySize, SMEM_O_BYTES);

    dim3 t(256);

    // Weight splits (1 launch)
    split_weights_kernel<<<dim3((HD * CC + 255) / 256, 4), t>>>(
        Wq, Wk, Wv, Wp, Wqh, Wql, Wkh, Wkl, Wvh, Wvl, Wph, Wpl);

    // Input transposes+splits (1 launch)
    transpose_split_in_kernel<<<dim3(32, 8, 2 * BB), dim3(32, 8)>>>(
        x, y, Xth, Xtl, Yth, Ytl);

    // All projections (Q hi/lo, K single, V single, YP) in 1 launch
    proj_all_kernel<<<dim3(8, 50, BB), t, SMEM_BYTES>>>(
        Wqh, Wql, Wkh, Wkl, Wvh, Wvl, Wph, Wpl,
        Xth, Xtl, Yth, Ytl, bq, bk, bv,
        Qh, Ql, Kh, Vh, YP);

    // S = Q^T K (fp16 asymmetric 2-term, 2-stage)
    attn_s_kernel<<<dim3(8, 8, ZZ), t, SMEM_S_BYTES>>>(Qh, Ql, Kh, S);

    // softmax -> P hi/lo (fp16)
    softmax_kernel<<<ZZ * NN_ / 8, t>>>(S, Ph, Pl);

    // O = P V^T + epilogue (fp16 asymmetric 2-term, 2-stage)
    attn_o_kernel<<<dim3(2, 16, ZZ), t, SMEM_O_BYTES>>>(Ph, Pl, Vh, YP, gamma, out);
}